// round 3
// baseline (speedup 1.0000x reference)
#include <cuda_runtime.h>

#define N_NODES 100000
#define N_EDGES 1600000
#define HIDDEN_DIM 64
#define EIGS_DIM 32

// Scratch (device globals: no allocation allowed)
__device__ int g_deg[N_NODES];     // degree per destination node
__device__ int g_start[N_NODES];   // segment start per node (valid partition)
__device__ int g_cursor[N_NODES];  // scatter cursor per node
__device__ int g_total;            // global allocation counter for block bases
__device__ int g_i1s[N_EDGES];     // source node per edge, grouped by destination

// ---------------------------------------------------------------------------
// K1: histogram of destination degrees
// ---------------------------------------------------------------------------
__global__ void hist_kernel(const int* __restrict__ idx)
{
    int e = blockIdx.x * blockDim.x + threadIdx.x;
    if (e < N_EDGES) atomicAdd(&g_deg[idx[e]], 1);
}

// ---------------------------------------------------------------------------
// K2: per-block scan of degrees; block base allocated via one global atomic.
// Segment placement order is non-deterministic across blocks, but every node
// gets a disjoint, correctly-sized range — which is all the algorithm needs.
// ---------------------------------------------------------------------------
__global__ void scan_kernel()
{
    __shared__ int warp_sums[32];
    __shared__ int block_base;

    int i    = blockIdx.x * blockDim.x + threadIdx.x;
    int lane = threadIdx.x & 31;
    int wid  = threadIdx.x >> 5;
    int nwarps = blockDim.x >> 5;

    int d = (i < N_NODES) ? g_deg[i] : 0;

    // warp-inclusive scan
    int x = d;
    #pragma unroll
    for (int o = 1; o < 32; o <<= 1) {
        int y = __shfl_up_sync(0xffffffffu, x, o);
        if (lane >= o) x += y;
    }
    if (lane == 31) warp_sums[wid] = x;
    __syncthreads();

    if (wid == 0) {
        int s = (lane < nwarps) ? warp_sums[lane] : 0;
        #pragma unroll
        for (int o = 1; o < 32; o <<= 1) {
            int y = __shfl_up_sync(0xffffffffu, s, o);
            if (lane >= o) s += y;
        }
        warp_sums[lane] = s;  // inclusive scan of warp totals
    }
    __syncthreads();

    if (threadIdx.x == 0)
        block_base = atomicAdd(&g_total, warp_sums[nwarps - 1]);
    __syncthreads();

    int excl = (x - d) + (wid > 0 ? warp_sums[wid - 1] : 0) + block_base;
    if (i < N_NODES) {
        g_start[i]  = excl;
        g_cursor[i] = excl;
    }
}

// ---------------------------------------------------------------------------
// K3: scatter source indices into destination-grouped segments
// ---------------------------------------------------------------------------
__global__ void scatter_kernel(const int* __restrict__ idx)
{
    int e = blockIdx.x * blockDim.x + threadIdx.x;
    if (e >= N_EDGES) return;
    int i0 = idx[e];
    int i1 = idx[N_EDGES + e];
    int pos = atomicAdd(&g_cursor[i0], 1);
    g_i1s[pos] = i1;
}

// ---------------------------------------------------------------------------
// K4: fused per-node attention. 16 threads per node (2 nodes per warp).
// One loop over the node's edges: gather k/eigs/v rows, compute logit,
// accumulate denom and unnormalized weighted V-sum in registers, then
// scale once and store the output row. Zero atomics, zero scratch.
// ---------------------------------------------------------------------------
__global__ void fused_kernel(const float* __restrict__ q,
                             const float* __restrict__ k,
                             const float* __restrict__ v,
                             const float* __restrict__ eigs,
                             const float* __restrict__ lambda0,
                             float* __restrict__ out)
{
    int gid  = blockIdx.x * blockDim.x + threadIdx.x;
    int node = gid >> 4;
    if (node >= N_NODES) return;
    int lane = gid & 15;

    float lam = expf(lambda0[0]);
    int start = g_start[node];
    int deg   = g_deg[node];
    int end   = start + deg;

    // per-node operands in registers: lane's float4 of q, and of eigs (lanes 0-7)
    float4 q4 = ((const float4*)q)[(size_t)node * (HIDDEN_DIM / 4) + lane];
    float4 eg = make_float4(0.f, 0.f, 0.f, 0.f);
    if (lane < 8)
        eg = ((const float4*)eigs)[(size_t)node * (EIGS_DIM / 4) + lane];

    float denom = 0.0f;
    float4 acc  = make_float4(0.f, 0.f, 0.f, 0.f);

    for (int j = start; j < end; j++) {
        int i1 = g_i1s[j];

        float4 k4 = ((const float4*)k)[(size_t)i1 * (HIDDEN_DIM / 4) + lane];
        float t = (q4.x * k4.x + q4.y * k4.y + q4.z * k4.z + q4.w * k4.w) * 0.125f;

        if (lane < 8) {
            float4 eb = ((const float4*)eigs)[(size_t)i1 * (EIGS_DIM / 4) + lane];
            t += lam * (eg.x * eb.x + eg.y * eb.y + eg.z * eb.z + eg.w * eb.w);
        }

        // 16-lane butterfly: all lanes end with the full logit
        t += __shfl_xor_sync(0xffffffffu, t, 1);
        t += __shfl_xor_sync(0xffffffffu, t, 2);
        t += __shfl_xor_sync(0xffffffffu, t, 4);
        t += __shfl_xor_sync(0xffffffffu, t, 8);

        // clip(exp(s), -5, 5): exp >= 0, only upper bound binds
        float e = fminf(expf(t), 5.0f);
        denom += e;

        float4 vv = ((const float4*)v)[(size_t)i1 * (HIDDEN_DIM / 4) + lane];
        acc.x += e * vv.x;
        acc.y += e * vv.y;
        acc.z += e * vv.z;
        acc.w += e * vv.w;
    }

    float inv = 1.0f / ((denom == 0.0f) ? 1.0f : denom);
    acc.x *= inv; acc.y *= inv; acc.z *= inv; acc.w *= inv;

    ((float4*)out)[(size_t)node * (HIDDEN_DIM / 4) + lane] = acc;
}

extern "C" void kernel_launch(void* const* d_in, const int* in_sizes, int n_in,
                              void* d_out, int out_size)
{
    const float* q       = (const float*)d_in[0];
    const float* k       = (const float*)d_in[1];
    const float* v       = (const float*)d_in[2];
    const float* eigs    = (const float*)d_in[3];
    const float* lambda0 = (const float*)d_in[4];
    const int*   idx     = (const int*)d_in[5];

    void *deg_ptr = nullptr, *total_ptr = nullptr;
    cudaGetSymbolAddress(&deg_ptr, g_deg);
    cudaGetSymbolAddress(&total_ptr, g_total);
    cudaMemsetAsync(deg_ptr, 0, N_NODES * sizeof(int));
    cudaMemsetAsync(total_ptr, 0, sizeof(int));

    {
        int block = 256;
        int grid = (N_EDGES + block - 1) / block;
        hist_kernel<<<grid, block>>>(idx);
    }
    {
        int block = 1024;
        int grid = (N_NODES + block - 1) / block;
        scan_kernel<<<grid, block>>>();
    }
    {
        int block = 256;
        int grid = (N_EDGES + block - 1) / block;
        scatter_kernel<<<grid, block>>>(idx);
    }
    {
        long long total = (long long)N_NODES * 16;
        int block = 256;
        int grid = (int)((total + block - 1) / block);
        fused_kernel<<<grid, block>>>(q, k, v, eigs, lambda0, (float*)d_out);
    }
}

// round 4
// speedup vs baseline: 1.9013x; 1.9013x over previous
#include <cuda_runtime.h>

#define N_NODES 100000
#define N_EDGES 1600000
#define HIDDEN_DIM 64
#define EIGS_DIM 32

// Scratch (device globals: no allocation allowed)
__device__ float g_e[N_EDGES];     // per-edge numerator, edge order
__device__ int   g_deg[N_NODES];   // degree per destination node
__device__ int   g_start[N_NODES]; // segment start per node
__device__ int   g_cursor[N_NODES];
__device__ int   g_total;
__device__ int2  g_csr[N_EDGES];   // {i1, bitcast(e)} grouped by destination

// ---------------------------------------------------------------------------
// Pass 1: per-edge logits (8 threads/edge) + degree histogram (lane 0).
// ---------------------------------------------------------------------------
__global__ void pass1_kernel(const float* __restrict__ q,
                             const float* __restrict__ k,
                             const float* __restrict__ eigs,
                             const float* __restrict__ lambda0,
                             const int* __restrict__ idx)
{
    int gid  = blockIdx.x * blockDim.x + threadIdx.x;
    int edge = gid >> 3;
    if (edge >= N_EDGES) return;
    int lane = gid & 7;

    int i0 = idx[edge];            // destination node
    int i1 = idx[N_EDGES + edge];  // source node

    const float4* q4 = (const float4*)q + (size_t)i0 * (HIDDEN_DIM / 4);
    const float4* k4 = (const float4*)k + (size_t)i1 * (HIDDEN_DIM / 4);

    float4 a0 = q4[lane * 2];
    float4 a1 = q4[lane * 2 + 1];
    float4 b0 = k4[lane * 2];
    float4 b1 = k4[lane * 2 + 1];

    float x = a0.x * b0.x + a0.y * b0.y + a0.z * b0.z + a0.w * b0.w
            + a1.x * b1.x + a1.y * b1.y + a1.z * b1.z + a1.w * b1.w;

    float4 ea = ((const float4*)eigs)[(size_t)i0 * (EIGS_DIM / 4) + lane];
    float4 eb = ((const float4*)eigs)[(size_t)i1 * (EIGS_DIM / 4) + lane];
    float y = ea.x * eb.x + ea.y * eb.y + ea.z * eb.z + ea.w * eb.w;

    float lam = expf(lambda0[0]);
    float t = x * 0.125f + lam * y;   // 1/sqrt(64) = 0.125

    t += __shfl_xor_sync(0xffffffffu, t, 1);
    t += __shfl_xor_sync(0xffffffffu, t, 2);
    t += __shfl_xor_sync(0xffffffffu, t, 4);

    if (lane == 0) {
        // clip(exp(s), -5, 5): exp >= 0 so only the upper bound binds
        g_e[edge] = fminf(expf(t), 5.0f);
        atomicAdd(&g_deg[i0], 1);
    }
}

// ---------------------------------------------------------------------------
// Scan: per-block scan of degrees; block base via one global atomic.
// Segment placement is a valid disjoint partition (order irrelevant).
// ---------------------------------------------------------------------------
__global__ void scan_kernel()
{
    __shared__ int warp_sums[32];
    __shared__ int block_base;

    int i    = blockIdx.x * blockDim.x + threadIdx.x;
    int lane = threadIdx.x & 31;
    int wid  = threadIdx.x >> 5;
    int nwarps = blockDim.x >> 5;

    int d = (i < N_NODES) ? g_deg[i] : 0;

    int x = d;
    #pragma unroll
    for (int o = 1; o < 32; o <<= 1) {
        int y = __shfl_up_sync(0xffffffffu, x, o);
        if (lane >= o) x += y;
    }
    if (lane == 31) warp_sums[wid] = x;
    __syncthreads();

    if (wid == 0) {
        int s = (lane < nwarps) ? warp_sums[lane] : 0;
        #pragma unroll
        for (int o = 1; o < 32; o <<= 1) {
            int y = __shfl_up_sync(0xffffffffu, s, o);
            if (lane >= o) s += y;
        }
        warp_sums[lane] = s;
    }
    __syncthreads();

    if (threadIdx.x == 0)
        block_base = atomicAdd(&g_total, warp_sums[nwarps - 1]);
    __syncthreads();

    int excl = (x - d) + (wid > 0 ? warp_sums[wid - 1] : 0) + block_base;
    if (i < N_NODES) {
        g_start[i]  = excl;
        g_cursor[i] = excl;
    }
}

// ---------------------------------------------------------------------------
// Scatter: pack {i1, e} into destination-grouped segments.
// ---------------------------------------------------------------------------
__global__ void scatter_kernel(const int* __restrict__ idx)
{
    int e = blockIdx.x * blockDim.x + threadIdx.x;
    if (e >= N_EDGES) return;
    int i0 = idx[e];
    int i1 = idx[N_EDGES + e];
    float ev = g_e[e];
    int pos = atomicAdd(&g_cursor[i0], 1);
    g_csr[pos] = make_int2(i1, __float_as_int(ev));
}

// ---------------------------------------------------------------------------
// Pass 2 (node-parallel): out[n] = (sum_j e_j * v[i1_j]) / (sum_j e_j)
// 16 threads/node. No shuffles, no atomics; loop iterations independent.
// ---------------------------------------------------------------------------
__global__ void pass2_kernel(const float* __restrict__ v,
                             float* __restrict__ out)
{
    int gid  = blockIdx.x * blockDim.x + threadIdx.x;
    int node = gid >> 4;
    if (node >= N_NODES) return;
    int lane = gid & 15;

    int start = g_start[node];
    int end   = start + g_deg[node];

    float denom = 0.0f;
    float4 acc  = make_float4(0.f, 0.f, 0.f, 0.f);

    const float4* v4 = (const float4*)v;

    int j = start;
    // unroll by 2 with independent loads for MLP
    for (; j + 2 <= end; j += 2) {
        int2 c0 = g_csr[j];
        int2 c1 = g_csr[j + 1];
        float  e0 = __int_as_float(c0.y);
        float  e1 = __int_as_float(c1.y);
        float4 v0 = v4[(size_t)c0.x * (HIDDEN_DIM / 4) + lane];
        float4 v1 = v4[(size_t)c1.x * (HIDDEN_DIM / 4) + lane];
        denom += e0 + e1;
        acc.x += e0 * v0.x + e1 * v1.x;
        acc.y += e0 * v0.y + e1 * v1.y;
        acc.z += e0 * v0.z + e1 * v1.z;
        acc.w += e0 * v0.w + e1 * v1.w;
    }
    for (; j < end; j++) {
        int2 c0 = g_csr[j];
        float  e0 = __int_as_float(c0.y);
        float4 v0 = v4[(size_t)c0.x * (HIDDEN_DIM / 4) + lane];
        denom += e0;
        acc.x += e0 * v0.x;
        acc.y += e0 * v0.y;
        acc.z += e0 * v0.z;
        acc.w += e0 * v0.w;
    }

    float inv = 1.0f / ((denom == 0.0f) ? 1.0f : denom);
    acc.x *= inv; acc.y *= inv; acc.z *= inv; acc.w *= inv;

    ((float4*)out)[(size_t)node * (HIDDEN_DIM / 4) + lane] = acc;
}

extern "C" void kernel_launch(void* const* d_in, const int* in_sizes, int n_in,
                              void* d_out, int out_size)
{
    const float* q       = (const float*)d_in[0];
    const float* k       = (const float*)d_in[1];
    const float* v       = (const float*)d_in[2];
    const float* eigs    = (const float*)d_in[3];
    const float* lambda0 = (const float*)d_in[4];
    const int*   idx     = (const int*)d_in[5];

    void *deg_ptr = nullptr, *total_ptr = nullptr;
    cudaGetSymbolAddress(&deg_ptr, g_deg);
    cudaGetSymbolAddress(&total_ptr, g_total);
    cudaMemsetAsync(deg_ptr, 0, N_NODES * sizeof(int));
    cudaMemsetAsync(total_ptr, 0, sizeof(int));

    {
        long long total = (long long)N_EDGES * 8;
        int block = 256;
        int grid = (int)((total + block - 1) / block);
        pass1_kernel<<<grid, block>>>(q, k, eigs, lambda0, idx);
    }
    {
        int block = 1024;
        int grid = (N_NODES + block - 1) / block;
        scan_kernel<<<grid, block>>>();
    }
    {
        int block = 256;
        int grid = (N_EDGES + block - 1) / block;
        scatter_kernel<<<grid, block>>>(idx);
    }
    {
        long long total = (long long)N_NODES * 16;
        int block = 256;
        int grid = (int)((total + block - 1) / block);
        pass2_kernel<<<grid, block>>>(v, (float*)d_out);
    }
}